// round 1
// baseline (speedup 1.0000x reference)
#include <cuda_runtime.h>

// Fixed problem shape: B=1, T=4, V=6, H=128, W=128
#define MAXID    8192
#define BT       4
#define M_ELEMS  393216
#define VHW      (M_ELEMS / BT)       // 98304
#define NSEG     (BT * MAXID + 1)     // 32769
#define REC      112                  // padded per-segment record (floats)
#define NEGF     (-1e30f)
#define THRF     2.0f
#define DUPF     0.05f

// Per-segment record layout (float slots):
//  [0..63]  dense   [64..79] inst   [80..87] motion  [88..91] rot
//  [92..94] center  [95..97] offset [98] opacity     [99..101] scale
//  [102..104] feat_dc [105] dyn     [106] d2 (sum e2) [107..111] pad

__device__ float         g_cnt[NSEG];
__device__ float         g_mx1[NSEG];
__device__ float4        g_e1c[NSEG];           // {d1, sum(cen*e1).xyz}
__device__ float         g_mx2[NSEG];
__device__ int           g_min[NSEG];
__device__ unsigned char g_act[M_ELEMS];
__device__ __align__(16) float g_sums[(size_t)NSEG * REC];

__device__ __forceinline__ void atomicMaxF(float* addr, float v) {
    // bit-exact float max via signed/unsigned int atomics
    if (v >= 0.0f) atomicMax((int*)addr, __float_as_int(v));
    else           atomicMin((unsigned int*)addr, __float_as_uint(v));
}

__device__ __forceinline__ void red4(float* addr, float a, float b, float c, float d) {
    asm volatile("red.global.add.v4.f32 [%0], {%1,%2,%3,%4};"
                 :: "l"(addr), "f"(a), "f"(b), "f"(c), "f"(d) : "memory");
}

__device__ __forceinline__ void red4v(float4* addr, float4 v) {
    asm volatile("red.global.add.v4.f32 [%0], {%1,%2,%3,%4};"
                 :: "l"(addr), "f"(v.x), "f"(v.y), "f"(v.z), "f"(v.w) : "memory");
}

// ---------------- Pass 0: init scratch ----------------
__global__ void k_init() {
    int t = blockIdx.x * blockDim.x + threadIdx.x;
    if (t < (int)((size_t)NSEG * REC)) g_sums[t] = 0.0f;
    if (t < NSEG) {
        g_cnt[t] = 0.0f;
        g_mx1[t] = NEGF;
        g_mx2[t] = NEGF;
        g_e1c[t] = make_float4(0.f, 0.f, 0.f, 0.f);
        g_min[t] = M_ELEMS;
    }
}

// ---------------- Pass 1: count + max1 ----------------
__global__ void k_p1(const int* __restrict__ ids, const float* __restrict__ kp) {
    int i = blockIdx.x * blockDim.x + threadIdx.x;
    if (i >= M_ELEMS) return;
    int id = ids[i];
    if (id >= 0) {
        int seg = (i / VHW) * MAXID + id;
        atomicAdd(&g_cnt[seg], 1.0f);
        atomicMaxF(&g_mx1[seg], kp[i]);
    }
}

// ---------------- Pass 2: d1 + sum(cen*e1) ----------------
__global__ void k_p2(const int* __restrict__ ids, const float* __restrict__ kp,
                     const float* __restrict__ cen) {
    int i = blockIdx.x * blockDim.x + threadIdx.x;
    if (i >= M_ELEMS) return;
    int id = ids[i];
    if (id >= 0) {
        int seg = (i / VHW) * MAXID + id;
        float e1 = expf(kp[i] - g_mx1[seg]);
        float c0 = cen[3 * (size_t)i + 0];
        float c1 = cen[3 * (size_t)i + 1];
        float c2 = cen[3 * (size_t)i + 2];
        red4v(&g_e1c[seg], make_float4(e1, c0 * e1, c1 * e1, c2 * e1));
    }
}

// ---------------- Pass 3: active mask + max2 ----------------
__global__ void k_p3(const int* __restrict__ ids, const float* __restrict__ kp,
                     const float* __restrict__ cen) {
    int i = blockIdx.x * blockDim.x + threadIdx.x;
    if (i >= M_ELEMS) return;
    int id = ids[i];
    unsigned char act = 0;
    if (id >= 0) {
        int seg = (i / VHW) * MAXID + id;
        if (g_cnt[seg] >= 2.0f) {
            float4 f = g_e1c[seg];
            float inv = (f.x > 0.0f) ? (1.0f / f.x) : 1.0f;
            float dx = cen[3 * (size_t)i + 0] - f.y * inv;
            float dy = cen[3 * (size_t)i + 1] - f.z * inv;
            float dz = cen[3 * (size_t)i + 2] - f.w * inv;
            float dist = sqrtf(dx * dx + dy * dy + dz * dz);
            if (dist <= THRF) {
                act = 1;
                atomicMaxF(&g_mx2[seg], kp[i]);
            }
        }
    }
    g_act[i] = act;
}

// ---------------- Pass 4: big weighted accumulate (v4 reds) ----------------
__global__ void k_p4(const float* __restrict__ dense, const float* __restrict__ cen,
                     const float* __restrict__ off,   const float* __restrict__ opa,
                     const float* __restrict__ sca,   const float* __restrict__ rot,
                     const float* __restrict__ fdc,   const float* __restrict__ kp,
                     const float* __restrict__ inst,  const float* __restrict__ mot,
                     const float* __restrict__ dyn,   const int* __restrict__ ids) {
    int i = blockIdx.x * blockDim.x + threadIdx.x;
    if (i >= M_ELEMS) return;
    if (!g_act[i]) return;

    int seg = (i / VHW) * MAXID + ids[i];
    float k0 = kp[i];
    float m2 = g_mx2[seg];
    float e2 = expf(k0 - m2);
    if (k0 >= m2) atomicMin(&g_min[seg], i);

    float* base = g_sums + (size_t)seg * REC;

    const float4* dv = (const float4*)(dense + (size_t)i * 64);
#pragma unroll
    for (int k = 0; k < 16; k++) {
        float4 v = dv[k];
        red4(base + 4 * k, v.x * e2, v.y * e2, v.z * e2, v.w * e2);
    }
    const float4* iv = (const float4*)(inst + (size_t)i * 16);
#pragma unroll
    for (int k = 0; k < 4; k++) {
        float4 v = iv[k];
        red4(base + 64 + 4 * k, v.x * e2, v.y * e2, v.z * e2, v.w * e2);
    }
    const float4* mv = (const float4*)(mot + (size_t)i * 8);
#pragma unroll
    for (int k = 0; k < 2; k++) {
        float4 v = mv[k];
        red4(base + 80 + 4 * k, v.x * e2, v.y * e2, v.z * e2, v.w * e2);
    }
    {
        float4 v = ((const float4*)(rot + (size_t)i * 4))[0];
        red4(base + 88, v.x * e2, v.y * e2, v.z * e2, v.w * e2);
    }
    float c0 = cen[3 * (size_t)i], c1 = cen[3 * (size_t)i + 1], c2 = cen[3 * (size_t)i + 2];
    float o0 = off[3 * (size_t)i], o1 = off[3 * (size_t)i + 1], o2 = off[3 * (size_t)i + 2];
    float op = opa[i];
    float s0 = sca[3 * (size_t)i], s1 = sca[3 * (size_t)i + 1], s2 = sca[3 * (size_t)i + 2];
    float f0 = fdc[3 * (size_t)i], f1 = fdc[3 * (size_t)i + 1], f2 = fdc[3 * (size_t)i + 2];
    float dn = dyn[i];
    red4(base + 92,  c0 * e2, c1 * e2, c2 * e2, o0 * e2);
    red4(base + 96,  o1 * e2, o2 * e2, op * e2, s0 * e2);
    red4(base + 100, s1 * e2, s2 * e2, f0 * e2, f1 * e2);
    red4(base + 104, f2 * e2, dn * e2, e2,      0.0f);
}

// ---------------- Pass 5: divide sums by d2 ----------------
__global__ void k_fin1() {
    int t = blockIdx.x * blockDim.x + threadIdx.x;
    if (t >= (int)((size_t)NSEG * REC)) return;
    int slot = t % REC;
    if (slot >= 106) return;
    int seg = t / REC;
    float d2 = g_sums[(size_t)seg * REC + 106];
    float inv = (d2 > 0.0f) ? (1.0f / d2) : 1.0f;
    g_sums[t] *= inv;
}

// ---------------- Pass 6: normalize rotation ----------------
__global__ void k_fin2() {
    int t = blockIdx.x * blockDim.x + threadIdx.x;
    if (t >= NSEG) return;
    float* r = g_sums + (size_t)t * REC + 88;
    float r0 = r[0], r1 = r[1], r2 = r[2], r3 = r[3];
    float n = sqrtf(r0 * r0 + r1 * r1 + r2 * r2 + r3 * r3);
    float inv = 1.0f / fmaxf(n, 1e-12f);
    r[0] = r0 * inv; r[1] = r1 * inv; r[2] = r2 * inv; r[3] = r3 * inv;
}

// ---------------- Pass 7: scatter outputs ----------------
__global__ void k_out(const float* __restrict__ dense, const float* __restrict__ cen,
                      const float* __restrict__ off,   const float* __restrict__ opa,
                      const float* __restrict__ sca,   const float* __restrict__ rot,
                      const float* __restrict__ fdc,   const float* __restrict__ kp,
                      const float* __restrict__ inst,  const float* __restrict__ mot,
                      const float* __restrict__ dyn,   const int* __restrict__ ids,
                      float* __restrict__ out) {
    int i = blockIdx.x * blockDim.x + threadIdx.x;
    if (i >= M_ELEMS) return;

    const size_t M = M_ELEMS;
    float* o_dense = out;
    float* o_cen   = out + 64 * M;
    float* o_off   = out + 67 * M;
    float* o_opa   = out + 70 * M;
    float* o_sca   = out + 71 * M;
    float* o_rot   = out + 74 * M;
    float* o_fdc   = out + 78 * M;
    float* o_kp    = out + 81 * M;
    float* o_inst  = out + 82 * M;
    float* o_mot   = out + 98 * M;
    float* o_dyn   = out + 106 * M;

    if (g_act[i]) {
        int seg = (i / VHW) * MAXID + ids[i];
        const float* r = g_sums + (size_t)seg * REC;
        float fac = (i == g_min[seg]) ? 1.0f : DUPF;

        float4* od = (float4*)(o_dense + (size_t)i * 64);
        const float4* rd = (const float4*)r;
#pragma unroll
        for (int k = 0; k < 16; k++) od[k] = rd[k];

        float4* oi = (float4*)(o_inst + (size_t)i * 16);
        const float4* ri = (const float4*)(r + 64);
#pragma unroll
        for (int k = 0; k < 4; k++) oi[k] = ri[k];

        float4* om = (float4*)(o_mot + (size_t)i * 8);
        const float4* rm = (const float4*)(r + 80);
        om[0] = rm[0]; om[1] = rm[1];

        ((float4*)(o_rot + (size_t)i * 4))[0] = ((const float4*)(r + 88))[0];

        o_cen[3 * (size_t)i + 0] = r[92];
        o_cen[3 * (size_t)i + 1] = r[93];
        o_cen[3 * (size_t)i + 2] = r[94];
        o_off[3 * (size_t)i + 0] = r[95];
        o_off[3 * (size_t)i + 1] = r[96];
        o_off[3 * (size_t)i + 2] = r[97];
        o_opa[i] = r[98] * fac;
        o_sca[3 * (size_t)i + 0] = r[99];
        o_sca[3 * (size_t)i + 1] = r[100];
        o_sca[3 * (size_t)i + 2] = r[101];
        o_fdc[3 * (size_t)i + 0] = r[102];
        o_fdc[3 * (size_t)i + 1] = r[103];
        o_fdc[3 * (size_t)i + 2] = r[104];
        o_kp[i]  = g_mx2[seg] * fac;
        o_dyn[i] = r[105];
    } else {
        float4* od = (float4*)(o_dense + (size_t)i * 64);
        const float4* sd = (const float4*)(dense + (size_t)i * 64);
#pragma unroll
        for (int k = 0; k < 16; k++) od[k] = sd[k];

        float4* oi = (float4*)(o_inst + (size_t)i * 16);
        const float4* si = (const float4*)(inst + (size_t)i * 16);
#pragma unroll
        for (int k = 0; k < 4; k++) oi[k] = si[k];

        float4* om = (float4*)(o_mot + (size_t)i * 8);
        const float4* sm = (const float4*)(mot + (size_t)i * 8);
        om[0] = sm[0]; om[1] = sm[1];

        ((float4*)(o_rot + (size_t)i * 4))[0] = ((const float4*)(rot + (size_t)i * 4))[0];

        o_cen[3 * (size_t)i + 0] = cen[3 * (size_t)i + 0];
        o_cen[3 * (size_t)i + 1] = cen[3 * (size_t)i + 1];
        o_cen[3 * (size_t)i + 2] = cen[3 * (size_t)i + 2];
        o_off[3 * (size_t)i + 0] = off[3 * (size_t)i + 0];
        o_off[3 * (size_t)i + 1] = off[3 * (size_t)i + 1];
        o_off[3 * (size_t)i + 2] = off[3 * (size_t)i + 2];
        o_opa[i] = opa[i];
        o_sca[3 * (size_t)i + 0] = sca[3 * (size_t)i + 0];
        o_sca[3 * (size_t)i + 1] = sca[3 * (size_t)i + 1];
        o_sca[3 * (size_t)i + 2] = sca[3 * (size_t)i + 2];
        o_fdc[3 * (size_t)i + 0] = fdc[3 * (size_t)i + 0];
        o_fdc[3 * (size_t)i + 1] = fdc[3 * (size_t)i + 1];
        o_fdc[3 * (size_t)i + 2] = fdc[3 * (size_t)i + 2];
        o_kp[i]  = kp[i];
        o_dyn[i] = dyn[i];
    }
}

extern "C" void kernel_launch(void* const* d_in, const int* in_sizes, int n_in,
                              void* d_out, int out_size) {
    const float* dense = (const float*)d_in[0];
    const float* cen   = (const float*)d_in[1];
    const float* off   = (const float*)d_in[2];
    const float* opa   = (const float*)d_in[3];
    const float* sca   = (const float*)d_in[4];
    const float* rot   = (const float*)d_in[5];
    const float* fdc   = (const float*)d_in[6];
    const float* kp    = (const float*)d_in[7];
    const float* inst  = (const float*)d_in[8];
    const float* mot   = (const float*)d_in[9];
    const float* dyn   = (const float*)d_in[10];
    const int*   ids   = (const int*)d_in[11];
    float* out = (float*)d_out;

    const int TB = 256;
    const int gM = (M_ELEMS + TB - 1) / TB;
    const int gR = ((int)((size_t)NSEG * REC) + TB - 1) / TB;
    const int gS = (NSEG + TB - 1) / TB;

    k_init<<<gR, TB>>>();
    k_p1<<<gM, TB>>>(ids, kp);
    k_p2<<<gM, TB>>>(ids, kp, cen);
    k_p3<<<gM, TB>>>(ids, kp, cen);
    k_p4<<<gM, TB>>>(dense, cen, off, opa, sca, rot, fdc, kp, inst, mot, dyn, ids);
    k_fin1<<<gR, TB>>>();
    k_fin2<<<gS, TB>>>();
    k_out<<<gM, TB>>>(dense, cen, off, opa, sca, rot, fdc, kp, inst, mot, dyn, ids, out);
}